// round 2
// baseline (speedup 1.0000x reference)
#include <cuda_runtime.h>

// TaylorActivation: out = Horner(x; c[0..8]), elementwise over 512x65536 fp32.
// Pure HBM-bound stream: 128 MiB in + 128 MiB out.

__global__ void __launch_bounds__(256, 8)
taylor_kernel(const float4* __restrict__ x,
              const float* __restrict__ w,
              float4* __restrict__ out,
              int n4)
{
    int i = blockIdx.x * blockDim.x + threadIdx.x;
    if (i >= n4) return;

    // Coefficients: 9 broadcast loads, L1/L2-resident after first warp.
    const float c0 = __ldg(&w[0]);
    const float c1 = __ldg(&w[1]);
    const float c2 = __ldg(&w[2]);
    const float c3 = __ldg(&w[3]);
    const float c4 = __ldg(&w[4]);
    const float c5 = __ldg(&w[5]);
    const float c6 = __ldg(&w[6]);
    const float c7 = __ldg(&w[7]);
    const float c8 = __ldg(&w[8]);

    float4 v = x[i];

    float4 r;
    r.x = c8; r.y = c8; r.z = c8; r.w = c8;

    // Horner: r = r*x + c[k], k = 7..0 (fully unrolled, 8 FMA per lane)
    r.x = fmaf(r.x, v.x, c7); r.y = fmaf(r.y, v.y, c7); r.z = fmaf(r.z, v.z, c7); r.w = fmaf(r.w, v.w, c7);
    r.x = fmaf(r.x, v.x, c6); r.y = fmaf(r.y, v.y, c6); r.z = fmaf(r.z, v.z, c6); r.w = fmaf(r.w, v.w, c6);
    r.x = fmaf(r.x, v.x, c5); r.y = fmaf(r.y, v.y, c5); r.z = fmaf(r.z, v.z, c5); r.w = fmaf(r.w, v.w, c5);
    r.x = fmaf(r.x, v.x, c4); r.y = fmaf(r.y, v.y, c4); r.z = fmaf(r.z, v.z, c4); r.w = fmaf(r.w, v.w, c4);
    r.x = fmaf(r.x, v.x, c3); r.y = fmaf(r.y, v.y, c3); r.z = fmaf(r.z, v.z, c3); r.w = fmaf(r.w, v.w, c3);
    r.x = fmaf(r.x, v.x, c2); r.y = fmaf(r.y, v.y, c2); r.z = fmaf(r.z, v.z, c2); r.w = fmaf(r.w, v.w, c2);
    r.x = fmaf(r.x, v.x, c1); r.y = fmaf(r.y, v.y, c1); r.z = fmaf(r.z, v.z, c1); r.w = fmaf(r.w, v.w, c1);
    r.x = fmaf(r.x, v.x, c0); r.y = fmaf(r.y, v.y, c0); r.z = fmaf(r.z, v.z, c0); r.w = fmaf(r.w, v.w, c0);

    out[i] = r;
}

extern "C" void kernel_launch(void* const* d_in, const int* in_sizes, int n_in,
                              void* d_out, int out_size)
{
    const float* x = (const float*)d_in[0];   // (512, 65536) fp32
    const float* w = (const float*)d_in[1];   // (9, 1) fp32
    float* out = (float*)d_out;

    int n = in_sizes[0];          // 33554432, divisible by 4
    int n4 = n / 4;               // 8388608

    const int threads = 256;
    int blocks = (n4 + threads - 1) / threads;   // 32768

    taylor_kernel<<<blocks, threads>>>(
        (const float4*)x, w, (float4*)out, n4);
}